// round 1
// baseline (speedup 1.0000x reference)
#include <cuda_runtime.h>
#include <cuda_bf16.h>

// Problem shapes (fixed by the dataset): B=16, T=512, D=384, MAX_LEN=4096
#define LR_B       16
#define LR_T       512
#define LR_D       384
#define LR_D4      (LR_D / 4)          // 96 float4 per row
#define LR_MAXLEN  4096
#define LR_NEXP    (LR_B * LR_MAXLEN * LR_D)   // 25,165,824 floats

// Scratch (no cudaMalloc allowed): token map per output position, and mel lens.
__device__ int g_tok_map[LR_B * LR_MAXLEN];
__device__ int g_mel[LR_B];

// ---------------------------------------------------------------------------
// Kernel A: per-batch inclusive scan of durations (T=512, one block per batch),
// then SCATTER token index into g_tok_map for every covered output position.
// Positions >= min(mel_len, max_len) get -1 (zero-fill marker).
// This replaces searchsorted: the token whose interval [cum[t-1], cum[t])
// contains pos is exactly searchsorted(cum, pos, 'right') for valid pos
// (zero-duration tokens write nothing, matching 'right' semantics).
// ---------------------------------------------------------------------------
__global__ void lr_scan_scatter_kernel(const int* __restrict__ durations) {
    __shared__ int s[LR_T];
    const int b = blockIdx.x;
    const int t = threadIdx.x;

    s[t] = durations[b * LR_T + t];
    __syncthreads();

    // Hillis-Steele inclusive scan over 512 elements
    #pragma unroll
    for (int off = 1; off < LR_T; off <<= 1) {
        int v = (t >= off) ? s[t - off] : 0;
        __syncthreads();
        s[t] += v;
        __syncthreads();
    }

    const int end   = s[t];
    const int start = (t == 0) ? 0 : s[t - 1];
    const int mel   = s[LR_T - 1];

    int* tm = g_tok_map + b * LR_MAXLEN;

    // Scatter: each thread writes its token's interval (duration in [0,8))
    for (int p = start; p < end && p < LR_MAXLEN; ++p)
        tm[p] = t;

    // Invalid tail -> -1
    const int lim = (mel < LR_MAXLEN) ? mel : LR_MAXLEN;
    for (int p = lim + t; p < LR_MAXLEN; p += LR_T)
        tm[p] = -1;

    if (t == 0) g_mel[b] = mel;
}

// ---------------------------------------------------------------------------
// Kernel B: flat vectorized gather-copy. One float4 per thread.
// row = b*MAX_LEN + pos ; col in [0,96). tok_map[row] is broadcast within the
// 96 threads of a row (L1 hit); encoder_out (12.6 MB) is L2-resident with
// ~3.5x reuse. Stores are perfectly coalesced 16B.
// ---------------------------------------------------------------------------
__global__ void lr_expand_kernel(const float4* __restrict__ enc,
                                 float4* __restrict__ out) {
    const int idx = blockIdx.x * blockDim.x + threadIdx.x;
    // total = LR_B * LR_MAXLEN * LR_D4 = 6,291,456 ; grid sized exactly
    const int row = idx / LR_D4;
    const int col = idx - row * LR_D4;

    const int tok = g_tok_map[row];
    float4 v = make_float4(0.f, 0.f, 0.f, 0.f);
    if (tok >= 0) {
        const int b = row >> 12;  // MAX_LEN = 4096
        v = enc[(b * LR_T + tok) * LR_D4 + col];
    }
    out[idx] = v;
}

// ---------------------------------------------------------------------------
// Kernel C: append mel_lens (int -> float) after the expanded block.
// ---------------------------------------------------------------------------
__global__ void lr_mel_kernel(float* __restrict__ out_tail) {
    const int i = threadIdx.x;
    if (i < LR_B) out_tail[i] = (float)g_mel[i];
}

extern "C" void kernel_launch(void* const* d_in, const int* in_sizes, int n_in,
                              void* d_out, int out_size) {
    const int* durations = (const int*)d_in[1];
    const float4* enc = (const float4*)d_in[0];
    float* out = (float*)d_out;

    lr_scan_scatter_kernel<<<LR_B, LR_T>>>(durations);

    const int total4 = LR_B * LR_MAXLEN * LR_D4;   // 6,291,456
    const int threads = 256;
    const int blocks = total4 / threads;           // 24576, exact
    lr_expand_kernel<<<blocks, threads>>>(enc, (float4*)out);

    // Second output (mel_lens) if the harness concatenated it into d_out
    if (out_size >= LR_NEXP + LR_B) {
        lr_mel_kernel<<<1, 32>>>(out + LR_NEXP);
    }
}

// round 2
// speedup vs baseline: 1.3672x; 1.3672x over previous
#include <cuda_runtime.h>
#include <cuda_bf16.h>

// Fixed shapes: B=16, T=512, D=384, MAX_LEN=4096
#define LR_B       16
#define LR_T       512
#define LR_D4      96                       // float4 per row
#define LR_MAXLEN  4096
#define LR_NEXP    (LR_B * LR_MAXLEN * 384) // 25,165,824 floats

#define NTOK        (LR_B * LR_T)           // 8192 token warps
#define NTOK_BLK    (NTOK / 8)              // 1024 blocks, 8 warps each
#define NROW        (LR_B * LR_MAXLEN)      // 65536 output rows
#define NZERO_BLK   (NROW / 8)              // 8192 blocks (worst case; early exit)

__device__ int g_cum[NTOK];   // inclusive cumsum of durations, flat [B*T]
__device__ int g_mel[LR_B];

// ---------------------------------------------------------------------------
// Kernel A: shfl-based inclusive scan per batch (3 barriers). Writes g_cum,
// g_mel, and mel_lens (as float) straight into the output tail.
// ---------------------------------------------------------------------------
__global__ void lr_scan_kernel(const int* __restrict__ durations,
                               float* __restrict__ out_tail) {
    __shared__ int wsum[16];
    const int b    = blockIdx.x;
    const int t    = threadIdx.x;       // 512 threads
    const int lane = t & 31;
    const int warp = t >> 5;

    int v = durations[b * LR_T + t];
    #pragma unroll
    for (int off = 1; off < 32; off <<= 1) {
        int n = __shfl_up_sync(0xffffffffu, v, off);
        if (lane >= off) v += n;
    }
    if (lane == 31) wsum[warp] = v;
    __syncthreads();
    if (warp == 0 && lane < 16) {
        int s = wsum[lane];
        #pragma unroll
        for (int off = 1; off < 16; off <<= 1) {
            int n = __shfl_up_sync(0xffffu, s, off, 16);
            if (lane >= off) s += n;
        }
        wsum[lane] = s;                 // inclusive warp totals
    }
    __syncthreads();

    const int cum = v + (warp ? wsum[warp - 1] : 0);
    g_cum[b * LR_T + t] = cum;

    if (t == 0) {
        const int mel = wsum[15];
        g_mel[b] = mel;
        if (out_tail) out_tail[b] = (float)mel;
    }
}

// ---------------------------------------------------------------------------
// Kernel B (fused scatter-copy + zero-fill), 256 thr = 8 warps/block.
//  blocks [0, NTOK_BLK):            warp per token; load row once (3xfloat4
//                                   per lane), store to its dur output rows.
//  blocks [NTOK_BLK, +NZERO_BLK):   warp per output row; zero if pos >= mel.
// Regions are disjoint: valid rows written by token warps, tail by zero warps.
// ---------------------------------------------------------------------------
__global__ void lr_expand_kernel(const float4* __restrict__ enc,
                                 float4* __restrict__ out) {
    const int warp = threadIdx.x >> 5;
    const int lane = threadIdx.x & 31;

    if (blockIdx.x < NTOK_BLK) {
        const int tok = blockIdx.x * 8 + warp;        // 0..8191
        const int b   = tok >> 9;
        const int t   = tok & 511;
        const int end   = g_cum[tok];
        const int start = t ? g_cum[tok - 1] : 0;
        if (start >= end) return;                     // dur == 0

        const float4* src = enc + (size_t)tok * LR_D4;
        const float4 v0 = src[lane];
        const float4 v1 = src[lane + 32];
        const float4 v2 = src[lane + 64];

        const int lim = (end < LR_MAXLEN) ? end : LR_MAXLEN;  // (never binds)
        float4* dst = out + ((size_t)(b << 12) + start) * LR_D4;
        for (int p = start; p < lim; ++p, dst += LR_D4) {
            dst[lane]      = v0;
            dst[lane + 32] = v1;
            dst[lane + 64] = v2;
        }
    } else {
        const int row = (blockIdx.x - NTOK_BLK) * 8 + warp;   // 0..65535
        const int b   = row >> 12;
        const int pos = row & 4095;
        if (pos < g_mel[b]) return;                   // valid region: skip

        const float4 z = make_float4(0.f, 0.f, 0.f, 0.f);
        float4* dst = out + (size_t)row * LR_D4;
        dst[lane]      = z;
        dst[lane + 32] = z;
        dst[lane + 64] = z;
    }
}

extern "C" void kernel_launch(void* const* d_in, const int* in_sizes, int n_in,
                              void* d_out, int out_size) {
    const float4* enc = (const float4*)d_in[0];
    const int* durations = (const int*)d_in[1];
    float* out = (float*)d_out;

    float* out_tail = (out_size >= LR_NEXP + LR_B) ? (out + LR_NEXP) : nullptr;

    lr_scan_kernel<<<LR_B, LR_T>>>(durations, out_tail);
    lr_expand_kernel<<<NTOK_BLK + NZERO_BLK, 256>>>(enc, (float4*)out);
}

// round 3
// speedup vs baseline: 1.3904x; 1.0170x over previous
#include <cuda_runtime.h>
#include <cuda_bf16.h>

// Fixed shapes: B=16, T=512, D=384, MAX_LEN=4096
#define LR_B       16
#define LR_T       512
#define LR_D4      96                       // float4 per row
#define LR_MAXLEN  4096
#define LR_NEXP    (LR_B * LR_MAXLEN * 384) // 25,165,824 floats

#define NTOK_BLK   1024                     // 8 token-warps per block, 8192 tokens
#define NZERO_BLK  8192                     // 8 rows per block, 65536 rows

// ---------------------------------------------------------------------------
// Single fused kernel. No global scratch, no second launch.
//  blocks [0, NTOK_BLK):   warp per token. Warp redundantly computes
//                          start = sum(dur[b][0..t-1]) via strided-load +
//                          shfl reduction (dur rows are 2KB, L2-resident),
//                          loads its enc row once, scatters it dur times.
//  blocks [NTOK_BLK, ...): 8 output rows per block. Warp 0 reduces the full
//                          512-dur row to mel[b] (int4 loads), broadcasts via
//                          smem; warps with pos >= mel write zeros.
//  Row ownership is disjoint: token warps cover pos < mel, zero warps the rest.
// ---------------------------------------------------------------------------
__global__ void lr_fused_kernel(const float4* __restrict__ enc,
                                const int*    __restrict__ dur,
                                float4*       __restrict__ out,
                                float*        __restrict__ out_tail) {
    const int warp = threadIdx.x >> 5;
    const int lane = threadIdx.x & 31;

    if (blockIdx.x < NTOK_BLK) {
        // ---- token path ----
        const int tok = blockIdx.x * 8 + warp;        // 0..8191
        const int b   = tok >> 9;
        const int t   = tok & 511;
        const int* __restrict__ db = dur + b * LR_T;

        const int d = db[t];                          // uniform -> broadcast load
        if (d == 0) return;

        int s = 0;
        for (int i = lane; i < t; i += 32) s += db[i];
        #pragma unroll
        for (int o = 16; o; o >>= 1) s += __shfl_down_sync(0xffffffffu, s, o);
        const int start = __shfl_sync(0xffffffffu, s, 0);
        const int end   = start + d;                  // max cum = 3584 < 4096

        const float4* src = enc + (size_t)tok * LR_D4;
        const float4 v0 = src[lane];
        const float4 v1 = src[lane + 32];
        const float4 v2 = src[lane + 64];

        float4* dst = out + ((size_t)(b << 12) + start) * LR_D4;
        for (int p = start; p < end; ++p, dst += LR_D4) {
            dst[lane]      = v0;
            dst[lane + 32] = v1;
            dst[lane + 64] = v2;
        }
    } else {
        // ---- zero-fill path ----
        __shared__ int s_mel;
        const int row0 = (blockIdx.x - NTOK_BLK) * 8; // 8 rows, same batch
        const int b    = row0 >> 12;

        if (warp == 0) {
            const int4* __restrict__ db4 = (const int4*)(dur + b * LR_T); // 128 int4
            int s = 0;
            #pragma unroll
            for (int i = 0; i < 4; ++i) {
                const int4 v = db4[lane + 32 * i];
                s += v.x + v.y + v.z + v.w;
            }
            #pragma unroll
            for (int o = 16; o; o >>= 1) s += __shfl_down_sync(0xffffffffu, s, o);
            if (lane == 0) {
                s_mel = s;
                if (out_tail && (row0 & 4095) == 0)   // first zero-block of batch
                    out_tail[b] = (float)s;
            }
        }
        __syncthreads();

        const int pos = (row0 & 4095) + warp;
        if (pos < s_mel) return;                      // valid region: token warps own it

        const float4 z = make_float4(0.f, 0.f, 0.f, 0.f);
        float4* dst = out + ((size_t)(row0 + warp)) * LR_D4;
        dst[lane]      = z;
        dst[lane + 32] = z;
        dst[lane + 64] = z;
    }
}

extern "C" void kernel_launch(void* const* d_in, const int* in_sizes, int n_in,
                              void* d_out, int out_size) {
    const float4* enc = (const float4*)d_in[0];
    const int* durations = (const int*)d_in[1];
    float* out = (float*)d_out;

    float* out_tail = (out_size >= LR_NEXP + LR_B) ? (out + LR_NEXP) : nullptr;

    lr_fused_kernel<<<NTOK_BLK + NZERO_BLK, 256>>>(enc, durations,
                                                   (float4*)out, out_tail);
}